// round 12
// baseline (speedup 1.0000x reference)
#include <cuda_runtime.h>

#define B 128
#define DF 2048
#define KSPLIT 128
#define KCHUNK 16           // DF / KSPLIT
#define NBLOCKS 128
#define NTHREADS 256
#define LDA 132             // padded SMEM row stride

// Scratch (static device globals; no allocation).
__device__ float g_Gp[KSPLIT * B * B];   // split-K partial Gram (8MB)
__device__ float g_G[B * B];             // reduced Gram
__device__ float g_part[NBLOCKS];        // per-block loss partials
__device__ unsigned g_bar[2];            // monotonic barrier counters (never reset)
__device__ unsigned g_fin;               // monotonic finalize counter (never reset)

// Monotonic grid barrier: no reset across graph replays (2^32 % 128 == 0).
__device__ __forceinline__ void grid_barrier(int which) {
    __syncthreads();
    if (threadIdx.x == 0) {
        __threadfence();                                   // release
        unsigned old = atomicAdd(&g_bar[which], 1u);
        unsigned target = old - (old & (NBLOCKS - 1u)) + NBLOCKS;
        while ((int)(*(volatile unsigned*)&g_bar[which] - target) < 0) {
            __nanosleep(64);
        }
        __threadfence();                                   // acquire
    }
    __syncthreads();
}

__global__ __launch_bounds__(NTHREADS) void fused_angle_loss(
    const float* __restrict__ X, float* __restrict__ out) {

    __shared__ float smemBuf[KCHUNK * LDA];   // 8.4KB, reused across phases
    const int b = blockIdx.x;
    const int t = threadIdx.x;

    // ============================ Phase 1: split-K Gram =====================
    // block b = z: FULL 128x128 output tile for k-chunk [16b, 16b+16).
    // 8x8 micro-tile per thread: 64 FMA per 4 LDS.128 (1 B/FMA) -> both
    // FFMA and LDS pipes at ~2048 cyc (half of the 64x64 scheme).
    // A and B rows come from the SAME SMEM X-slice (Gram symmetry).
    {
        const int kB = b * KCHUNK;
        float* As = smemBuf;                 // [k][row] k-major, stride LDA

        // Load X k-slice: 128 rows x 16 k = 512 float4; 2 per thread.
#pragma unroll
        for (int it = 0; it < 2; it++) {
            const int i   = t + it * NTHREADS;   // 0..511
            const int row = i >> 2;              // 0..127
            const int kq  = (i & 3) * 4;         // 0,4,8,12
            float4 v = *(const float4*)(X + (size_t)row * DF + kB + kq);
            As[(kq + 0) * LDA + row] = v.x; As[(kq + 1) * LDA + row] = v.y;
            As[(kq + 2) * LDA + row] = v.z; As[(kq + 3) * LDA + row] = v.w;
        }
        __syncthreads();

        const int r0 = (t >> 4) * 8;         // micro-tile rows r0..r0+7
        const int c0 = (t & 15) * 8;         // micro-tile cols c0..c0+7

        float acc[8][8] = {};
#pragma unroll
        for (int k = 0; k < KCHUNK; k++) {
            const float* row = &As[k * LDA];
            float4 a0 = *(const float4*)&row[r0];
            float4 a1 = *(const float4*)&row[r0 + 4];
            float4 b0 = *(const float4*)&row[c0];
            float4 b1 = *(const float4*)&row[c0 + 4];
            const float av[8] = {a0.x, a0.y, a0.z, a0.w, a1.x, a1.y, a1.z, a1.w};
            const float bv[8] = {b0.x, b0.y, b0.z, b0.w, b1.x, b1.y, b1.z, b1.w};
#pragma unroll
            for (int ii = 0; ii < 8; ii++)
#pragma unroll
                for (int jj = 0; jj < 8; jj++)
                    acc[ii][jj] = fmaf(av[ii], bv[jj], acc[ii][jj]);
        }

        float* dst = g_Gp + (size_t)b * (B * B);
#pragma unroll
        for (int ii = 0; ii < 8; ii++) {
            float4 v0 = make_float4(acc[ii][0], acc[ii][1], acc[ii][2], acc[ii][3]);
            float4 v1 = make_float4(acc[ii][4], acc[ii][5], acc[ii][6], acc[ii][7]);
            *(float4*)&dst[(r0 + ii) * B + c0]     = v0;
            *(float4*)&dst[(r0 + ii) * B + c0 + 4] = v1;
        }
    }

    grid_barrier(0);

    // ===================== Phase 2: split-K reduce (128 layers) =============
    // 4096 float4 outputs / 128 blocks = 32 per block. 256 threads:
    // f4c = t&31, z-group zg = t>>5 (0..7) sums 16 layers, then t<32
    // combines the 8 partials in fixed zg order (deterministic).
    {
        float4* part = (float4*)smemBuf;           // [8][32] float4 = 4KB
        const int f4c = t & 31;
        const int zg  = t >> 5;
        const int f4  = b * 32 + f4c;
        const float4* src = (const float4*)g_Gp;
        float4 s = make_float4(0.f, 0.f, 0.f, 0.f);
#pragma unroll
        for (int zz = 0; zz < 16; zz++) {
            float4 v = __ldcg(src + (size_t)(zg * 16 + zz) * 4096 + f4);
            s.x += v.x; s.y += v.y; s.z += v.z; s.w += v.w;
        }
        part[zg * 32 + f4c] = s;
        __syncthreads();
        if (t < 32) {
            float4 r = part[t];
#pragma unroll
            for (int zg2 = 1; zg2 < 8; zg2++) {
                float4 v = part[zg2 * 32 + t];
                r.x += v.x; r.y += v.y; r.z += v.z; r.w += v.w;
            }
            ((float4*)g_G)[f4] = r;
        }
    }

    grid_barrier(1);

    // ======================= Phase 3: loss (all 128 blocks) =================
    // b = group*8 + slice. Group g=(target,sub); slice s -> pairs
    // (j0,j1) = (16p+s, 16p+s+8) for the 7 p != target.
    // ALL global loads issued in one batch up front (single L2 round).
    {
        const int g    = b >> 3;
        const int s    = b & 7;
        const int tgt  = g >> 1;
        const int sb   = g & 1;
        const int base = tgt * 16 + sb * 8;
        const int k    = t & 127;
        const int h    = t >> 7;

        float* sS    = smemBuf;          // [128] mean row-dot (already /8)
        float* sInv  = smemBuf + 128;    // [128] 1/norm
        float* sDiag = smemBuf + 256;    // [128] G[k][k]
        float* red   = smemBuf + 384;    // [8]
        int*   sFlag = (int*)(smemBuf + 392);

        // ---- batched loads (independent; one MLP window) ----
        float rowv[8];
        float gv0[4], gv1[4];
        float dia = 0.f;

        if (h == 0) {
#pragma unroll
            for (int i = 0; i < 8; i++) rowv[i] = __ldcg(&g_G[(base + i) * B + k]);
        } else {
            dia = __ldcg(&g_G[k * B + k]);
        }
#pragma unroll
        for (int pi = 0; pi < 4; pi++) {
            const int p = h * 4 + pi;
            const int j0 = p * 16 + s;
            gv0[pi] = __ldcg(&g_G[j0 * B + k]);         // loaded even if p==tgt
            gv1[pi] = __ldcg(&g_G[(j0 + 8) * B + k]);
        }

        if (h == 0) {
            float sk = ((rowv[0] + rowv[1]) + (rowv[2] + rowv[3]))
                     + ((rowv[4] + rowv[5]) + (rowv[6] + rowv[7]));
            sS[k] = sk * 0.125f;
        } else {
            sDiag[k] = dia;
        }
        __syncthreads();

        float q = 0.f;
#pragma unroll
        for (int i = 0; i < 8; i++) q += sS[base + i];
        q *= 0.125f;

        if (h == 0) {
            const float n2 = sDiag[k] - 2.f * sS[k] + q;
            const float nr = sqrtf(fmaxf(n2, 0.f));
            sInv[k] = 1.f / fmaxf(nr, 1e-12f);
        }
        __syncthreads();

        const float sk   = sS[k];
        const float invk = sInv[k];
        float acc = 0.f;
#pragma unroll
        for (int pi = 0; pi < 4; pi++) {
            const int p = h * 4 + pi;
            if (p == tgt) continue;
            const int j0 = p * 16 + s;
            const int j1 = j0 + 8;
            const float a0 = (gv0[pi] - sS[j0] - sk + q) * (sInv[j0] * invk);
            const float a1 = (gv1[pi] - sS[j1] - sk + q) * (sInv[j1] * invk);
            acc += fabsf(a0 - a1);
        }

        // Deterministic block reduction over 256 threads.
#pragma unroll
        for (int o = 16; o > 0; o >>= 1) acc += __shfl_down_sync(0xffffffffu, acc, o);
        if ((t & 31) == 0) red[t >> 5] = acc;
        __syncthreads();

        if (t == 0) {
            float sum = 0.f;
#pragma unroll
            for (int w = 0; w < 8; w++) sum += red[w];
            g_part[b] = sum;
            __threadfence();
            unsigned old = atomicAdd(&g_fin, 1u);
            sFlag[0] = ((old & (NBLOCKS - 1u)) == (NBLOCKS - 1u)) ? 1 : 0;
        }
        __syncthreads();

        // ---- parallel deterministic finalize by the last-arriving block ----
        if (sFlag[0]) {
            float v = (t < NBLOCKS) ? __ldcg(&g_part[t]) : 0.f;
#pragma unroll
            for (int o = 16; o > 0; o >>= 1) v += __shfl_down_sync(0xffffffffu, v, o);
            if ((t & 31) == 0) red[t >> 5] = v;
            __syncthreads();
            if (t == 0) {
                float tot = ((red[0] + red[1]) + (red[2] + red[3]));
                out[0] = tot * (1.0f / 114688.0f);
            }
        }
    }
}

extern "C" void kernel_launch(void* const* d_in, const int* in_sizes, int n_in,
                              void* d_out, int out_size) {
    const float* X = (const float*)d_in[0];   // [128, 2048] fp32
    float* out = (float*)d_out;               // scalar loss

    fused_angle_loss<<<NBLOCKS, NTHREADS>>>(X, out);
}

// round 13
// speedup vs baseline: 1.1379x; 1.1379x over previous
#include <cuda_runtime.h>

#define B 128
#define DF 2048
#define KSPLIT 32
#define KCHUNK 64           // DF / KSPLIT
#define NBLOCKS 128
#define NTHREADS 256

// Scratch (static device globals; no allocation).
__device__ float g_Gp[KSPLIT * B * B];   // split-K partial Gram
__device__ float g_G[B * B];             // reduced Gram
__device__ float g_part[NBLOCKS];        // per-block loss partials
__device__ unsigned g_bar[2];            // monotonic barrier counters (never reset)
__device__ unsigned g_fin;               // monotonic finalize counter (never reset)

// Monotonic grid barrier: no reset across graph replays (2^32 % 128 == 0).
__device__ __forceinline__ void grid_barrier(int which) {
    __syncthreads();
    if (threadIdx.x == 0) {
        __threadfence();                                   // release
        unsigned old = atomicAdd(&g_bar[which], 1u);
        unsigned target = old - (old & (NBLOCKS - 1u)) + NBLOCKS;
        while ((int)(*(volatile unsigned*)&g_bar[which] - target) < 0) {
            __nanosleep(64);
        }
        __threadfence();                                   // acquire
    }
    __syncthreads();
}

__global__ __launch_bounds__(NTHREADS) void fused_angle_loss(
    const float* __restrict__ X, float* __restrict__ out) {

    __shared__ float smemBuf[2 * KCHUNK * 68];   // 34.8KB, reused across phases
    const int b = blockIdx.x;
    const int t = threadIdx.x;

    // ============================ Phase 1: split-K Gram =====================
    // block b: z = b>>2 (K chunk), tile index b&3 -> 64x64 output tile.
    // All 8 LDG.128 issued in ONE batch (single cold-memory round), then STS.
    {
        const int z     = b >> 2;
        const int tileR = ((b >> 1) & 1) * 64;
        const int tileC = (b & 1) * 64;
        const int kBase = z * KCHUNK;

        float (*As)[68] = (float(*)[68])smemBuf;
        float (*Bs)[68] = (float(*)[68])(smemBuf + KCHUNK * 68);

        const int lr = t >> 2;            // 0..63 : row within tile
        const int c4 = (t & 3) * 4;       // 0,4,8,12 : k sub-offset

        float4 va[4], vb[4];
#pragma unroll
        for (int i = 0; i < 4; i++) {     // batched: 8 independent LDG.128
            const int k0 = c4 + 16 * i;
            va[i] = *(const float4*)(X + (size_t)(tileR + lr) * DF + kBase + k0);
            vb[i] = *(const float4*)(X + (size_t)(tileC + lr) * DF + kBase + k0);
        }
#pragma unroll
        for (int i = 0; i < 4; i++) {
            const int k0 = c4 + 16 * i;
            As[k0 + 0][lr] = va[i].x; As[k0 + 1][lr] = va[i].y;
            As[k0 + 2][lr] = va[i].z; As[k0 + 3][lr] = va[i].w;
            Bs[k0 + 0][lr] = vb[i].x; Bs[k0 + 1][lr] = vb[i].y;
            Bs[k0 + 2][lr] = vb[i].z; Bs[k0 + 3][lr] = vb[i].w;
        }
        __syncthreads();

        const int r0 = (t >> 4) * 4;
        const int c0 = (t & 15) * 4;
        float acc[4][4] = {};
#pragma unroll 16
        for (int k = 0; k < KCHUNK; k++) {
            float4 a  = *(const float4*)&As[k][r0];
            float4 bb = *(const float4*)&Bs[k][c0];
            const float av[4] = {a.x, a.y, a.z, a.w};
            const float bv[4] = {bb.x, bb.y, bb.z, bb.w};
#pragma unroll
            for (int ii = 0; ii < 4; ii++)
#pragma unroll
                for (int jj = 0; jj < 4; jj++)
                    acc[ii][jj] = fmaf(av[ii], bv[jj], acc[ii][jj]);
        }

        float* dst = g_Gp + (size_t)z * (B * B);
#pragma unroll
        for (int ii = 0; ii < 4; ii++) {
            float4 v = make_float4(acc[ii][0], acc[ii][1], acc[ii][2], acc[ii][3]);
            *(float4*)&dst[(tileR + r0 + ii) * B + tileC + c0] = v;
        }
    }

    grid_barrier(0);

    // ===================== Phase 2: split-K reduce (all 128 blocks) =========
    // 4096 float4 outputs / 128 blocks = 32 per block. 4 warps: f4c = t&31,
    // z-group zg = t>>5 (0..3) sums 8 layers; t<32 combines the 4 partials
    // in fixed zg order (deterministic). Chain depth 32 -> 8.
    {
        float4* part = (float4*)smemBuf;           // [4][32] float4 = 2KB
        if (t < 128) {
            const int f4c = t & 31;
            const int zg  = t >> 5;
            const int f4  = b * 32 + f4c;
            const float4* src = (const float4*)g_Gp;
            float4 s = make_float4(0.f, 0.f, 0.f, 0.f);
#pragma unroll
            for (int zz = 0; zz < 8; zz++) {
                float4 v = __ldcg(src + (size_t)(zg * 8 + zz) * 4096 + f4);
                s.x += v.x; s.y += v.y; s.z += v.z; s.w += v.w;
            }
            part[zg * 32 + f4c] = s;
        }
        __syncthreads();
        if (t < 32) {
            float4 r = part[t];
#pragma unroll
            for (int zg2 = 1; zg2 < 4; zg2++) {
                float4 v = part[zg2 * 32 + t];
                r.x += v.x; r.y += v.y; r.z += v.z; r.w += v.w;
            }
            ((float4*)g_G)[b * 32 + t] = r;
        }
    }

    grid_barrier(1);

    // ======================= Phase 3: loss (all 128 blocks) =================
    // b = group*8 + slice. Group g=(target,sub); slice s -> pairs
    // (j0,j1) = (16p+s, 16p+s+8) for the 7 p != target.
    // ALL global loads issued in one batch up front (single L2 round).
    {
        const int g    = b >> 3;
        const int s    = b & 7;
        const int tgt  = g >> 1;
        const int sb   = g & 1;
        const int base = tgt * 16 + sb * 8;
        const int k    = t & 127;
        const int h    = t >> 7;

        float* sS    = smemBuf;          // [128] mean row-dot (already /8)
        float* sInv  = smemBuf + 128;    // [128] 1/norm
        float* sDiag = smemBuf + 256;    // [128] G[k][k]
        float* red   = smemBuf + 384;    // [8]
        int*   sFlag = (int*)(smemBuf + 392);

        // ---- batched loads (independent; one MLP window) ----
        float rowv[8];
        float gv0[4], gv1[4];
        float dia = 0.f;

        if (h == 0) {
#pragma unroll
            for (int i = 0; i < 8; i++) rowv[i] = __ldcg(&g_G[(base + i) * B + k]);
        } else {
            dia = __ldcg(&g_G[k * B + k]);
        }
#pragma unroll
        for (int pi = 0; pi < 4; pi++) {
            const int p = h * 4 + pi;
            const int j0 = p * 16 + s;
            gv0[pi] = __ldcg(&g_G[j0 * B + k]);         // loaded even if p==tgt
            gv1[pi] = __ldcg(&g_G[(j0 + 8) * B + k]);
        }
        __syncthreads();    // phase-2 smem reads complete before overwrite

        if (h == 0) {
            float sk = ((rowv[0] + rowv[1]) + (rowv[2] + rowv[3]))
                     + ((rowv[4] + rowv[5]) + (rowv[6] + rowv[7]));
            sS[k] = sk * 0.125f;
        } else {
            sDiag[k] = dia;
        }
        __syncthreads();

        float q = 0.f;
#pragma unroll
        for (int i = 0; i < 8; i++) q += sS[base + i];
        q *= 0.125f;

        if (h == 0) {
            const float n2 = sDiag[k] - 2.f * sS[k] + q;
            const float nr = sqrtf(fmaxf(n2, 0.f));
            sInv[k] = 1.f / fmaxf(nr, 1e-12f);
        }
        __syncthreads();

        const float sk   = sS[k];
        const float invk = sInv[k];
        float acc = 0.f;
#pragma unroll
        for (int pi = 0; pi < 4; pi++) {
            const int p = h * 4 + pi;
            if (p == tgt) continue;
            const int j0 = p * 16 + s;
            const int j1 = j0 + 8;
            const float a0 = (gv0[pi] - sS[j0] - sk + q) * (sInv[j0] * invk);
            const float a1 = (gv1[pi] - sS[j1] - sk + q) * (sInv[j1] * invk);
            acc += fabsf(a0 - a1);
        }

        // Deterministic block reduction over 256 threads.
#pragma unroll
        for (int o = 16; o > 0; o >>= 1) acc += __shfl_down_sync(0xffffffffu, acc, o);
        if ((t & 31) == 0) red[t >> 5] = acc;
        __syncthreads();

        if (t == 0) {
            float sum = 0.f;
#pragma unroll
            for (int w = 0; w < 8; w++) sum += red[w];
            g_part[b] = sum;
            __threadfence();
            unsigned old = atomicAdd(&g_fin, 1u);
            sFlag[0] = ((old & (NBLOCKS - 1u)) == (NBLOCKS - 1u)) ? 1 : 0;
        }
        __syncthreads();

        // ---- parallel deterministic finalize by the last-arriving block ----
        if (sFlag[0]) {
            float v = (t < NBLOCKS) ? __ldcg(&g_part[t]) : 0.f;
#pragma unroll
            for (int o = 16; o > 0; o >>= 1) v += __shfl_down_sync(0xffffffffu, v, o);
            if ((t & 31) == 0) red[t >> 5] = v;
            __syncthreads();
            if (t == 0) {
                float tot = ((red[0] + red[1]) + (red[2] + red[3]));
                out[0] = tot * (1.0f / 114688.0f);
            }
        }
    }
}

extern "C" void kernel_launch(void* const* d_in, const int* in_sizes, int n_in,
                              void* d_out, int out_size) {
    const float* X = (const float*)d_in[0];   // [128, 2048] fp32
    float* out = (float*)d_out;               // scalar loss

    fused_angle_loss<<<NBLOCKS, NTHREADS>>>(X, out);
}

// round 14
// speedup vs baseline: 1.1429x; 1.0043x over previous
#include <cuda_runtime.h>

#define B 128
#define DF 2048
#define KSPLIT 64
#define KCHUNK 32           // DF / KSPLIT
#define NBLOCKS 256
#define NTHREADS 256

// Scratch (static device globals; no allocation).
__device__ float g_Gp[KSPLIT * B * B];   // split-K partial Gram (4MB)
__device__ float g_G[B * B];             // reduced Gram
__device__ float g_part[NBLOCKS];        // per-block loss partials
__device__ unsigned g_bar[2];            // monotonic barrier counters (never reset)
__device__ unsigned g_fin;               // monotonic finalize counter (never reset)

// Monotonic grid barrier: no reset across graph replays (2^32 % 256 == 0).
__device__ __forceinline__ void grid_barrier(int which) {
    __syncthreads();
    if (threadIdx.x == 0) {
        __threadfence();                                   // release
        unsigned old = atomicAdd(&g_bar[which], 1u);
        unsigned target = old - (old & (NBLOCKS - 1u)) + NBLOCKS;
        while ((int)(*(volatile unsigned*)&g_bar[which] - target) < 0) {
            __nanosleep(64);
        }
        __threadfence();                                   // acquire
    }
    __syncthreads();
}

__global__ __launch_bounds__(NTHREADS) void fused_angle_loss(
    const float* __restrict__ X, float* __restrict__ out) {

    __shared__ float smemBuf[2 * KCHUNK * 68];   // 17.4KB -> 2 CTAs/SM fit easily
    const int b = blockIdx.x;
    const int t = threadIdx.x;

    // ============================ Phase 1: split-K Gram =====================
    // block b: z = b>>2 (K chunk of 32), tile index b&3 -> 64x64 output tile.
    // 256 blocks => ~2 CTAs/SM: co-resident CTAs hide each other's memory
    // latency and barrier spin. All 4 LDG.128 issued in ONE batch.
    {
        const int z     = b >> 2;
        const int tileR = ((b >> 1) & 1) * 64;
        const int tileC = (b & 1) * 64;
        const int kBase = z * KCHUNK;

        float (*As)[68] = (float(*)[68])smemBuf;
        float (*Bs)[68] = (float(*)[68])(smemBuf + KCHUNK * 68);

        float4 va[2], vb[2];
#pragma unroll
        for (int it = 0; it < 2; it++) {         // batched: 4 independent LDG.128
            const int i   = t + it * NTHREADS;   // 0..511
            const int row = i >> 3;              // 0..63
            const int kq  = (i & 7) * 4;         // 0..28
            va[it] = *(const float4*)(X + (size_t)(tileR + row) * DF + kBase + kq);
            vb[it] = *(const float4*)(X + (size_t)(tileC + row) * DF + kBase + kq);
        }
#pragma unroll
        for (int it = 0; it < 2; it++) {
            const int i   = t + it * NTHREADS;
            const int row = i >> 3;
            const int kq  = (i & 7) * 4;
            As[kq + 0][row] = va[it].x; As[kq + 1][row] = va[it].y;
            As[kq + 2][row] = va[it].z; As[kq + 3][row] = va[it].w;
            Bs[kq + 0][row] = vb[it].x; Bs[kq + 1][row] = vb[it].y;
            Bs[kq + 2][row] = vb[it].z; Bs[kq + 3][row] = vb[it].w;
        }
        __syncthreads();

        const int r0 = (t >> 4) * 4;
        const int c0 = (t & 15) * 4;
        float acc[4][4] = {};
#pragma unroll 8
        for (int k = 0; k < KCHUNK; k++) {
            float4 a  = *(const float4*)&As[k][r0];
            float4 bb = *(const float4*)&Bs[k][c0];
            const float av[4] = {a.x, a.y, a.z, a.w};
            const float bv[4] = {bb.x, bb.y, bb.z, bb.w};
#pragma unroll
            for (int ii = 0; ii < 4; ii++)
#pragma unroll
                for (int jj = 0; jj < 4; jj++)
                    acc[ii][jj] = fmaf(av[ii], bv[jj], acc[ii][jj]);
        }

        float* dst = g_Gp + (size_t)z * (B * B);
#pragma unroll
        for (int ii = 0; ii < 4; ii++) {
            float4 v = make_float4(acc[ii][0], acc[ii][1], acc[ii][2], acc[ii][3]);
            *(float4*)&dst[(tileR + r0 + ii) * B + tileC + c0] = v;
        }
    }

    grid_barrier(0);

    // ===================== Phase 2: split-K reduce (64 layers) ==============
    // 4096 float4 outputs / 256 blocks = 16 per block. t<128: f4c = t&15,
    // z-group zg = t>>4 (0..7) sums 8 layers; t<16 combines the 8 partials
    // in fixed zg order (deterministic).
    {
        float4* part = (float4*)smemBuf;           // [8][16] float4 = 2KB
        if (t < 128) {
            const int f4c = t & 15;
            const int zg  = t >> 4;
            const int f4  = b * 16 + f4c;
            const float4* src = (const float4*)g_Gp;
            float4 s = make_float4(0.f, 0.f, 0.f, 0.f);
#pragma unroll
            for (int zz = 0; zz < 8; zz++) {
                float4 v = __ldcg(src + (size_t)(zg * 8 + zz) * 4096 + f4);
                s.x += v.x; s.y += v.y; s.z += v.z; s.w += v.w;
            }
            part[zg * 16 + f4c] = s;
        }
        __syncthreads();
        if (t < 16) {
            float4 r = part[t];
#pragma unroll
            for (int zg2 = 1; zg2 < 8; zg2++) {
                float4 v = part[zg2 * 16 + t];
                r.x += v.x; r.y += v.y; r.z += v.z; r.w += v.w;
            }
            ((float4*)g_G)[b * 16 + t] = r;
        }
    }

    grid_barrier(1);

    // ======================= Phase 3: loss (all 256 blocks) =================
    // b = group*16 + slice2; slice2 = s*2 + hh. Group g=(target,sub); pair
    // rows (j0,j1) = (16p+s, 16p+s+8) for p in [4hh, 4hh+4) \ {tgt}.
    // Threads: k = t&127, half h = t>>7 -> p = 4hh + 2h + pi, pi in {0,1}.
    {
        const int g    = b >> 4;
        const int sl   = b & 15;
        const int s    = sl >> 1;
        const int hh   = sl & 1;
        const int tgt  = g >> 1;
        const int sb   = g & 1;
        const int base = tgt * 16 + sb * 8;
        const int k    = t & 127;
        const int h    = t >> 7;

        float* sS    = smemBuf;          // [128] mean row-dot (already /8)
        float* sInv  = smemBuf + 128;    // [128] 1/norm
        float* sDiag = smemBuf + 256;    // [128] G[k][k]
        float* red   = smemBuf + 384;    // [8]
        int*   sFlag = (int*)(smemBuf + 392);

        // ---- batched loads (independent; one MLP window) ----
        float rowv[8];
        float gv0[2], gv1[2];
        float dia = 0.f;

        if (h == 0) {
#pragma unroll
            for (int i = 0; i < 8; i++) rowv[i] = __ldcg(&g_G[(base + i) * B + k]);
        } else {
            dia = __ldcg(&g_G[k * B + k]);
        }
#pragma unroll
        for (int pi = 0; pi < 2; pi++) {
            const int p  = hh * 4 + h * 2 + pi;
            const int j0 = p * 16 + s;
            gv0[pi] = __ldcg(&g_G[j0 * B + k]);         // loaded even if p==tgt
            gv1[pi] = __ldcg(&g_G[(j0 + 8) * B + k]);
        }
        __syncthreads();    // phase-2 smem reads complete before overwrite

        if (h == 0) {
            float sk = ((rowv[0] + rowv[1]) + (rowv[2] + rowv[3]))
                     + ((rowv[4] + rowv[5]) + (rowv[6] + rowv[7]));
            sS[k] = sk * 0.125f;
        } else {
            sDiag[k] = dia;
        }
        __syncthreads();

        float q = 0.f;
#pragma unroll
        for (int i = 0; i < 8; i++) q += sS[base + i];
        q *= 0.125f;

        if (h == 0) {
            const float n2 = sDiag[k] - 2.f * sS[k] + q;
            const float nr = sqrtf(fmaxf(n2, 0.f));
            sInv[k] = 1.f / fmaxf(nr, 1e-12f);
        }
        __syncthreads();

        const float sk   = sS[k];
        const float invk = sInv[k];
        float acc = 0.f;
#pragma unroll
        for (int pi = 0; pi < 2; pi++) {
            const int p = hh * 4 + h * 2 + pi;
            if (p == tgt) continue;
            const int j0 = p * 16 + s;
            const int j1 = j0 + 8;
            const float a0 = (gv0[pi] - sS[j0] - sk + q) * (sInv[j0] * invk);
            const float a1 = (gv1[pi] - sS[j1] - sk + q) * (sInv[j1] * invk);
            acc += fabsf(a0 - a1);
        }

        // Deterministic block reduction over 256 threads.
#pragma unroll
        for (int o = 16; o > 0; o >>= 1) acc += __shfl_down_sync(0xffffffffu, acc, o);
        if ((t & 31) == 0) red[t >> 5] = acc;
        __syncthreads();

        if (t == 0) {
            float sum = 0.f;
#pragma unroll
            for (int w = 0; w < 8; w++) sum += red[w];
            g_part[b] = sum;
            __threadfence();
            unsigned old = atomicAdd(&g_fin, 1u);
            sFlag[0] = ((old & (NBLOCKS - 1u)) == (NBLOCKS - 1u)) ? 1 : 0;
        }
        __syncthreads();

        // ---- parallel deterministic finalize by the last-arriving block ----
        if (sFlag[0]) {
            float v = (t < NBLOCKS) ? __ldcg(&g_part[t]) : 0.f;
#pragma unroll
            for (int o = 16; o > 0; o >>= 1) v += __shfl_down_sync(0xffffffffu, v, o);
            if ((t & 31) == 0) red[t >> 5] = v;
            __syncthreads();
            if (t == 0) {
                float tot = ((red[0] + red[1]) + (red[2] + red[3]))
                          + ((red[4] + red[5]) + (red[6] + red[7]));
                out[0] = tot * (1.0f / 114688.0f);
            }
        }
    }
}

extern "C" void kernel_launch(void* const* d_in, const int* in_sizes, int n_in,
                              void* d_out, int out_size) {
    const float* X = (const float*)d_in[0];   // [128, 2048] fp32
    float* out = (float*)d_out;               // scalar loss

    fused_angle_loss<<<NBLOCKS, NTHREADS>>>(X, out);
}